// round 11
// baseline (speedup 1.0000x reference)
#include <cuda_runtime.h>
#include <cuda_bf16.h>

// Inputs (metadata order):
//   d_in[0] = x            float32 [65536]
//   d_in[1] = edge_weights float32 [16777216]
//   d_in[2] = bias         float32 [65536]
//   d_in[3] = src          int32   [16777216]
//   d_in[4] = dst          int32   [16777216]
// Output: out[i] = bias[i] + sum_{e: dst[e]==i} x[src[e]]*edge_weights[e]
//
// R11: the separate reduce kernel has a hard ~8us floor (launch + tail drain
// + L2-cold refetch). Fuse it: the scatter grid is one resident wave
// (148 CTAs x 1024 thr), so a software grid barrier is legal. After the
// barrier the same CTAs reduce the 16 replicas (L2-hot), add bias, store out
// directly (no atomics), and re-zero the replicas inline (restores the BSS
// "g_rep==0 at entry" invariant; no zero kernel, no bias prologue).
// Barrier uses a monotonic ticket counter -> safe under graph replay.

#define NODES      65536
#define REPLICAS   16
#define COLS4      (NODES / 4)            // 16384 float4 columns
#define SMEM_NODES 57344                  // 224KB of x in smem
#define SMEM_BYTES (SMEM_NODES * 4)
#define GRID_CTAS  148

__device__ float        g_rep[REPLICAS * NODES];   // 4MB scratch, BSS-zeroed
__device__ unsigned int g_barrier;                 // monotonic ticket counter

__global__ __launch_bounds__(1024) void fused_scatter_reduce_kernel(
        const float* __restrict__ x,
        const float* __restrict__ ew,
        const int*   __restrict__ src,
        const int*   __restrict__ dst,
        const float* __restrict__ bias,
        float* __restrict__ out,
        int n) {
    extern __shared__ float sx[];   // 57344 floats

    const int stride = gridDim.x * blockDim.x;
    const int gtid   = blockIdx.x * blockDim.x + threadIdx.x;

    // Prologue: cooperative coalesced load of x[0 .. SMEM_NODES) into smem.
    {
        const float4* x4 = reinterpret_cast<const float4*>(x);
        float4* sx4 = reinterpret_cast<float4*>(sx);
        for (int i = threadIdx.x; i < SMEM_NODES / 4; i += blockDim.x)
            sx4[i] = x4[i];
    }
    __syncthreads();

    const int n4 = n >> 2;
    const float4* __restrict__ ew4 = reinterpret_cast<const float4*>(ew);
    const int4*   __restrict__ s4  = reinterpret_cast<const int4*>(src);
    const int4*   __restrict__ d4  = reinterpret_cast<const int4*>(dst);

    // Replica fixed per warp, decorrelated across warps AND CTAs.
    const int warp = threadIdx.x >> 5;
    float* rep = g_rep + ((blockIdx.x + warp) & (REPLICAS - 1)) * NODES;

    for (int i = gtid; i < n4; i += stride) {
        int4   s = __ldcs(&s4[i]);
        float4 w = __ldcs(&ew4[i]);
        int4   d = __ldcs(&d4[i]);

        // Gather: smem for the low 87.5% of node ids, global for the rest.
        int c0 = (s.x < SMEM_NODES) ? s.x : 0;
        int c1 = (s.y < SMEM_NODES) ? s.y : 0;
        int c2 = (s.z < SMEM_NODES) ? s.z : 0;
        int c3 = (s.w < SMEM_NODES) ? s.w : 0;
        float x0 = sx[c0];
        float x1 = sx[c1];
        float x2 = sx[c2];
        float x3 = sx[c3];
        if (s.x >= SMEM_NODES) x0 = __ldg(&x[s.x]);
        if (s.y >= SMEM_NODES) x1 = __ldg(&x[s.y]);
        if (s.z >= SMEM_NODES) x2 = __ldg(&x[s.z]);
        if (s.w >= SMEM_NODES) x3 = __ldg(&x[s.w]);

        atomicAdd(&rep[d.x], w.x * x0);
        atomicAdd(&rep[d.y], w.y * x1);
        atomicAdd(&rep[d.z], w.z * x2);
        atomicAdd(&rep[d.w], w.w * x3);
    }

    // Tail (n % 4)
    for (int e = (n4 << 2) + gtid; e < n; e += stride) {
        int s = src[e];
        float xv = (s < SMEM_NODES) ? sx[s] : __ldg(&x[s]);
        atomicAdd(&rep[dst[e]], ew[e] * xv);
    }

    // ---- Grid-wide software barrier (single resident wave) ----
    __threadfence();                  // order prior REDGs before arrive
    __syncthreads();
    if (threadIdx.x == 0) {
        unsigned ticket = atomicAdd(&g_barrier, 1u);
        unsigned target = ticket - (ticket % GRID_CTAS) + GRID_CTAS;
        while (true) {
            unsigned v = *reinterpret_cast<volatile unsigned*>(&g_barrier);
            if ((v - target) < 0x80000000u) break;   // v >= target (mod 2^32)
            __nanosleep(64);
        }
    }
    __syncthreads();
    __threadfence();                  // acquire side

    // ---- In-kernel reduction: out = bias + sum of replicas; rezero ----
    {
        const float4* bias4 = reinterpret_cast<const float4*>(bias);
        float4* out4 = reinterpret_cast<float4*>(out);
        float4* rep4 = reinterpret_cast<float4*>(g_rep);

        for (int i = gtid; i < COLS4; i += stride) {
            float4 v[REPLICAS];
#pragma unroll
            for (int r = 0; r < REPLICAS; ++r)
                v[r] = rep4[r * COLS4 + i];
#pragma unroll
            for (int r = 0; r < REPLICAS; ++r)
                rep4[r * COLS4 + i] = make_float4(0.f, 0.f, 0.f, 0.f);

            float4 acc = bias4[i];
#pragma unroll
            for (int r = 0; r < REPLICAS; ++r) {
                acc.x += v[r].x; acc.y += v[r].y;
                acc.z += v[r].z; acc.w += v[r].w;
            }
            out4[i] = acc;
        }
    }
}

// Generic fallback for unexpected shapes (does not touch g_rep/g_barrier).
__global__ __launch_bounds__(256) void scatter_fallback_kernel(
        const float* __restrict__ x,
        const float* __restrict__ ew,
        const int*   __restrict__ src,
        const int*   __restrict__ dst,
        float* __restrict__ out,
        int n) {
    const int stride = gridDim.x * blockDim.x;
    for (int e = blockIdx.x * blockDim.x + threadIdx.x; e < n; e += stride) {
        atomicAdd(&out[dst[e]], ew[e] * __ldg(&x[src[e]]));
    }
}

__global__ void init_out_kernel(const float* __restrict__ bias,
                                float* __restrict__ out, int n) {
    int i = blockIdx.x * blockDim.x + threadIdx.x;
    if (i < n) out[i] = bias[i];
}

extern "C" void kernel_launch(void* const* d_in, const int* in_sizes, int n_in,
                              void* d_out, int out_size) {
    const float* x    = (const float*)d_in[0];
    const float* ew   = (const float*)d_in[1];
    const float* bias = (const float*)d_in[2];
    const int*   src  = (const int*)d_in[3];
    const int*   dst  = (const int*)d_in[4];
    float* out = (float*)d_out;

    const int n_nodes = in_sizes[0];
    const int n_edges = in_sizes[1];

    if (n_nodes == NODES) {
        static bool attr_set = false;
        if (!attr_set) {
            cudaFuncSetAttribute(fused_scatter_reduce_kernel,
                                 cudaFuncAttributeMaxDynamicSharedMemorySize,
                                 SMEM_BYTES);
            attr_set = true;
        }
        fused_scatter_reduce_kernel<<<GRID_CTAS, 1024, SMEM_BYTES>>>(
            x, ew, src, dst, bias, out, n_edges);
    } else {
        init_out_kernel<<<(n_nodes + 255) / 256, 256>>>(bias, out, n_nodes);
        int threads = 256;
        int blocks  = 2048;
        int max_blocks = (n_edges + threads - 1) / threads;
        if (blocks > max_blocks) blocks = max_blocks;
        if (blocks < 1) blocks = 1;
        scatter_fallback_kernel<<<blocks, threads>>>(x, ew, src, dst, out, n_edges);
    }
}